// round 14
// baseline (speedup 1.0000x reference)
#include <cuda_runtime.h>
#include <cuda_fp16.h>
#include <cstdint>

// Problem constants
#define BB   4
#define SS   2048
#define HH   16
#define DH   64
#define DM   1024
#define BHT  (BB*HH)          // 64
#define NX   (BB*SS*DM)       // 8388608
#define NW   (DM*DM)          // 1048576
#define NH   ((size_t)BB*HH*SS*DH)
#define K8E  0.18033688011112042f   // 0.125 * log2(e)
#define L2E  1.4426950408889634f    // log2(e)

// Scratch (device globals, fp16)
__device__ __half g_xh0[NX], g_xh1[NX], g_xh2[NX];            // fp16 inputs
__device__ __half g_wh0[NW], g_wh1[NW], g_wh2[NW], g_wh3[NW]; // fp16 weights
__device__ __half g_qh[NH], g_kh[NH];                         // [bh][s][dh]
__device__ __half g_vt[NH];                                   // [bh][dh][s]  (V^T)
__device__ __half g_ctx[NH];                                  // [bh][s][dh]
__device__ __half g_mh[(size_t)SS*SS];                        // fp16 mask

// ---------------------------------------------------------------------------
// helpers
// ---------------------------------------------------------------------------
__device__ __forceinline__ void mma16(float c[4], const uint32_t a[4], const uint32_t b[2]) {
    asm volatile(
        "mma.sync.aligned.m16n8k16.row.col.f32.f16.f16.f32 "
        "{%0,%1,%2,%3},{%4,%5,%6,%7},{%8,%9},{%0,%1,%2,%3};"
        : "+f"(c[0]), "+f"(c[1]), "+f"(c[2]), "+f"(c[3])
        : "r"(a[0]), "r"(a[1]), "r"(a[2]), "r"(a[3]), "r"(b[0]), "r"(b[1]));
}
// exp(c*0.125 + m) via base-2 degree-4 Taylor (|f|<=0.5, rel err <= 4.3e-5)
__device__ __forceinline__ float pexp(float c, float m) {
    float y = fmaf(c, K8E, m * L2E);
    float r = rintf(y);
    float f = y - r;
    float p = fmaf(0.009618129f, f, 0.055504109f);
    p = fmaf(p, f, 0.240226507f);
    p = fmaf(p, f, 0.693147181f);
    p = fmaf(p, f, 1.0f);
    return p * __int_as_float(((int)r + 127) << 23);
}
__device__ __forceinline__ void cpa16(uint32_t saddr, const void* g) {
    asm volatile("cp.async.ca.shared.global [%0], [%1], 16;" :: "r"(saddr), "l"(g));
}
#define CP_COMMIT asm volatile("cp.async.commit_group;")
#define CP_WAIT0  asm volatile("cp.async.wait_group 0;")
#define CP_WAIT1  asm volatile("cp.async.wait_group 1;")
__device__ __forceinline__ uint32_t h2u(__half2 h) { return *(uint32_t*)&h; }
// streaming (evict-first) float2 store
__device__ __forceinline__ void stcs2(float* p, float2 v) {
    asm volatile("st.global.cs.v2.f32 [%0], {%1, %2};" :: "l"(p), "f"(v.x), "f"(v.y) : "memory");
}

// ---------------------------------------------------------------------------
// K0: convert inputs + weights + mask to fp16
// ---------------------------------------------------------------------------
__global__ void k_prep(const float* __restrict__ q, const float* __restrict__ k,
                       const float* __restrict__ v, const float* __restrict__ wq,
                       const float* __restrict__ wk, const float* __restrict__ wv,
                       const float* __restrict__ wo, const float* __restrict__ mask)
{
    int z = blockIdx.z;
    size_t i4 = (size_t)blockIdx.x * blockDim.x + threadIdx.x;
    const float4* src; __half* dst; size_t n4;
    switch (z) {
        case 0: src = (const float4*)q;    dst = g_xh0; n4 = NX / 4; break;
        case 1: src = (const float4*)k;    dst = g_xh1; n4 = NX / 4; break;
        case 2: src = (const float4*)v;    dst = g_xh2; n4 = NX / 4; break;
        case 3: src = (const float4*)wq;   dst = g_wh0; n4 = NW / 4; break;
        case 4: src = (const float4*)wk;   dst = g_wh1; n4 = NW / 4; break;
        case 5: src = (const float4*)wv;   dst = g_wh2; n4 = NW / 4; break;
        case 6: src = (const float4*)wo;   dst = g_wh3; n4 = NW / 4; break;
        default: src = (const float4*)mask; dst = g_mh; n4 = (size_t)SS * SS / 4; break;
    }
    if (i4 < n4) {
        float4 a = src[i4];
        __half2 lo = __floats2half2_rn(a.x, a.y);
        __half2 hi = __floats2half2_rn(a.z, a.w);
        uint2 w = make_uint2(h2u(lo), h2u(hi));
        *(uint2*)&dst[i4 * 4] = w;
    }
}

// ---------------------------------------------------------------------------
// K1: fused QKV projection, fp16 m16n8k16. (round-10 proven version)
// ---------------------------------------------------------------------------
__global__ __launch_bounds__(256, 2) void k_qkv_proj(
    const float* __restrict__ bq, const float* __restrict__ bk,
    const float* __restrict__ bv)
{
    __shared__ uint32_t As[2][2560];
    __shared__ uint32_t Bs[2][2560];
    int z = blockIdx.z;
    const __half* X  = (z == 0) ? g_xh0 : (z == 1) ? g_xh1 : g_xh2;
    const __half* W  = (z == 0) ? g_wh0 : (z == 1) ? g_wh1 : g_wh2;
    const float*  Bi = (z == 0) ? bq : (z == 1) ? bk : bv;

    int tid = threadIdx.x;
    int lane = tid & 31, wid = tid >> 5;
    int g = lane >> 2, ct = lane & 3;
    int mb = (wid >> 2) * 64, nb = (wid & 3) * 32;
    int m0 = blockIdx.y * 128, n0 = blockIdx.x * 128;

    uint32_t asb = (uint32_t)__cvta_generic_to_shared(&As[0][0]);
    uint32_t bsb = (uint32_t)__cvta_generic_to_shared(&Bs[0][0]);

    float c[4][4][4];
    #pragma unroll
    for (int i = 0; i < 4; i++)
        #pragma unroll
        for (int j = 0; j < 4; j++)
            #pragma unroll
            for (int t = 0; t < 4; t++) c[i][j][t] = 0.0f;

    #define QLOAD(st_, k0_) do {                                                \
        _Pragma("unroll")                                                       \
        for (int it = 0; it < 2; it++) {                                        \
            int sl = tid + it * 256;                                            \
            int r = sl >> 2, ch = sl & 3;                                       \
            cpa16(asb + ((st_) * 2560 + r * 20 + ch * 4) * 4,                   \
                  X + (size_t)(m0 + r) * DM + (k0_) + ch * 8);                  \
            cpa16(bsb + ((st_) * 2560 + r * 20 + ch * 4) * 4,                   \
                  W + (size_t)(n0 + r) * DM + (k0_) + ch * 8);                  \
        }                                                                       \
    } while (0)

    QLOAD(0, 0);
    CP_COMMIT;

    for (int k0 = 0, st = 0; k0 < DM; k0 += 32, st ^= 1) {
        CP_WAIT0;
        __syncthreads();
        if (k0 + 32 < DM) QLOAD(st ^ 1, k0 + 32);
        CP_COMMIT;
        const uint32_t* Af = &As[st][0];
        const uint32_t* Bf = &Bs[st][0];
        #pragma unroll
        for (int kc = 0; kc < 2; kc++) {
            uint32_t af[4][4], bf[4][2];
            #pragma unroll
            for (int i = 0; i < 4; i++) {
                int r0 = (mb + i * 16 + g) * 20 + kc * 8 + ct;
                af[i][0] = Af[r0];       af[i][1] = Af[r0 + 160];
                af[i][2] = Af[r0 + 4];   af[i][3] = Af[r0 + 164];
            }
            #pragma unroll
            for (int j = 0; j < 4; j++) {
                int b0 = (nb + j * 8 + g) * 20 + kc * 8 + ct;
                bf[j][0] = Bf[b0]; bf[j][1] = Bf[b0 + 4];
            }
            #pragma unroll
            for (int i = 0; i < 4; i++)
                #pragma unroll
                for (int j = 0; j < 4; j++) mma16(c[i][j], af[i], bf[j]);
        }
    }
    #undef QLOAD
    __syncthreads();
    #pragma unroll
    for (int i = 0; i < 4; i++) {
        int row = m0 + mb + i * 16 + g;
        int b_ = row >> 11, s_ = row & (SS - 1);
        #pragma unroll
        for (int j = 0; j < 4; j++) {
            int col = n0 + nb + j * 8 + ct * 2;
            int h = col >> 6, dh = col & 63;
            float2 bi = *(const float2*)&Bi[col];
            float v0 = c[i][j][0] + bi.x, v1 = c[i][j][1] + bi.y;
            float v2 = c[i][j][2] + bi.x, v3 = c[i][j][3] + bi.y;
            if (z == 2) {
                size_t tb = ((size_t)(b_ * HH + h) * DH + dh) * SS;
                g_vt[tb + s_]            = __float2half_rn(v0);
                g_vt[tb + SS + s_]       = __float2half_rn(v1);
                g_vt[tb + s_ + 8]        = __float2half_rn(v2);
                g_vt[tb + SS + s_ + 8]   = __float2half_rn(v3);
            } else {
                __half* O = (z == 0) ? g_qh : g_kh;
                size_t base = ((size_t)(b_ * HH + h) * SS + s_) * DH + dh;
                *(uint32_t*)&O[base]          = h2u(__floats2half2_rn(v0, v1));
                *(uint32_t*)&O[base + 8 * DH] = h2u(__floats2half2_rn(v2, v3));
            }
        }
    }
}

// ---------------------------------------------------------------------------
// K2: fused attention, fp16, 64-q-row CTA, 2 CTAs/SM. fp16 mask loads.
// ---------------------------------------------------------------------------
#define AQ  0
#define AK  2304
#define AV  11520
#define ARD AK
#define ARP 15872
#define AIV 16000
#define AT_WORDS 16064
#define AT_BYTES (AT_WORDS * 4)

__global__ __launch_bounds__(256, 2) void k_attn(float* __restrict__ score)
{
    extern __shared__ uint32_t sm[];
    uint32_t* Qs = sm + AQ;
    uint32_t* Vt = sm + AV;
    float* redc  = (float*)(sm + ARD);
    float* rowp  = (float*)(sm + ARP);
    float* invs  = (float*)(sm + AIV);
    uint32_t smb = (uint32_t)__cvta_generic_to_shared(sm);

    int bh = blockIdx.y, q0 = blockIdx.x * 64;
    const __half* Q = g_qh + (size_t)bh * SS * DH;
    const __half* K = g_kh + (size_t)bh * SS * DH;
    const __half* V = g_vt + (size_t)bh * DH * SS;   // [dh][s]

    int tid = threadIdx.x, lane = tid & 31, wid = tid >> 5;
    int g = lane >> 2, ct = lane & 3;
    int mb = (wid & 3) * 16;      // q strip (16 rows)
    int nw = wid >> 2;            // n strip 0/1 (64 cols)
    int nb = nw * 64;

    // Q tile -> smem
    #pragma unroll
    for (int it = 0; it < 2; it++) {
        int sl = tid + it * 256;
        int r = sl >> 3, ch = sl & 7;
        cpa16(smb + (AQ + r * 36 + ch * 4) * 4, Q + (size_t)(q0 + r) * DH + ch * 8);
    }

    #define KLOAD(st_, n0_) do {                                                \
        _Pragma("unroll")                                                       \
        for (int it = 0; it < 4; it++) {                                        \
            int sl = tid + it * 256;                                            \
            int r = sl >> 3, ch = sl & 7;                                       \
            cpa16(smb + (AK + (st_) * 4608 + r * 36 + ch * 4) * 4,              \
                  K + (size_t)((n0_) + r) * DH + ch * 8);                       \
        }                                                                       \
    } while (0)
    #define VLOAD(n0_) do {                                                     \
        _Pragma("unroll")                                                       \
        for (int it = 0; it < 4; it++) {                                        \
            int sl = tid + it * 256;                                            \
            int r = sl >> 4, ch = sl & 15;                                      \
            cpa16(smb + (AV + r * 68 + ch * 4) * 4,                             \
                  V + (size_t)r * SS + (n0_) + ch * 8);                         \
        }                                                                       \
    } while (0)

    float c[8][4];
    float rs0 = 0.0f, rs1 = 0.0f;

    // ---------------- Pass A: row sums ----------------
    KLOAD(0, 0);
    CP_COMMIT;
    for (int n0 = 0, st = 0; n0 < SS; n0 += 128, st ^= 1) {
        CP_WAIT0;
        __syncthreads();
        if (n0 + 128 < SS) KLOAD(st ^ 1, n0 + 128);
        CP_COMMIT;
        const uint32_t* Kf = sm + AK + st * 4608;
        #pragma unroll
        for (int j = 0; j < 8; j++)
            #pragma unroll
            for (int t = 0; t < 4; t++) c[j][t] = 0.0f;
        #pragma unroll
        for (int kc = 0; kc < 4; kc++) {
            uint32_t af[4], bf[8][2];
            int r0 = (mb + g) * 36 + kc * 8 + ct;
            af[0] = Qs[r0];     af[1] = Qs[r0 + 288];
            af[2] = Qs[r0 + 4]; af[3] = Qs[r0 + 292];
            #pragma unroll
            for (int j = 0; j < 8; j++) {
                int b0 = (nb + j * 8 + g) * 36 + kc * 8 + ct;
                bf[j][0] = Kf[b0]; bf[j][1] = Kf[b0 + 4];
            }
            #pragma unroll
            for (int j = 0; j < 8; j++) mma16(c[j], af, bf[j]);
        }
        {
            int row = q0 + mb + g;
            #pragma unroll
            for (int j = 0; j < 8; j++) {
                int colg = n0 + nb + j * 8 + ct * 2;
                float2 mk0 = __half22float2(*(const __half2*)&g_mh[(size_t)row * SS + colg]);
                rs0 += pexp(c[j][0], mk0.x) + pexp(c[j][1], mk0.y);
                float2 mk1 = __half22float2(*(const __half2*)&g_mh[(size_t)(row + 8) * SS + colg]);
                rs1 += pexp(c[j][2], mk1.x) + pexp(c[j][3], mk1.y);
            }
        }
    }
    {
        float v = rs0;
        v += __shfl_xor_sync(0xffffffff, v, 1);
        v += __shfl_xor_sync(0xffffffff, v, 2);
        if (ct == 0) rowp[(mb + g) * 2 + nw] = v;
        v = rs1;
        v += __shfl_xor_sync(0xffffffff, v, 1);
        v += __shfl_xor_sync(0xffffffff, v, 2);
        if (ct == 0) rowp[(mb + 8 + g) * 2 + nw] = v;
    }
    __syncthreads();
    if (tid < 64) invs[tid] = 1.0f / (rowp[tid * 2] + rowp[tid * 2 + 1]);

    // ---------------- Pass B: score + ctx ----------------
    float d[8][4];
    #pragma unroll
    for (int j = 0; j < 8; j++)
        #pragma unroll
        for (int t = 0; t < 4; t++) d[j][t] = 0.0f;

    size_t sbase = (size_t)bh * SS * SS;

    KLOAD(0, 0);
    CP_COMMIT;
    for (int n0 = 0, st = 0; n0 < SS; n0 += 128, st ^= 1) {
        CP_WAIT0;            // K_cur ready
        __syncthreads();     // prev PV readers of Vt done; invs visible (iter 0)
        VLOAD(n0);
        CP_COMMIT;
        if (n0 + 128 < SS) KLOAD(st ^ 1, n0 + 128);
        CP_COMMIT;

        const uint32_t* Kf = sm + AK + st * 4608;
        #pragma unroll
        for (int j = 0; j < 8; j++)
            #pragma unroll
            for (int t = 0; t < 4; t++) c[j][t] = 0.0f;
        #pragma unroll
        for (int kc = 0; kc < 4; kc++) {
            uint32_t af[4], bf[8][2];
            int r0 = (mb + g) * 36 + kc * 8 + ct;
            af[0] = Qs[r0];     af[1] = Qs[r0 + 288];
            af[2] = Qs[r0 + 4]; af[3] = Qs[r0 + 292];
            #pragma unroll
            for (int j = 0; j < 8; j++) {
                int b0 = (nb + j * 8 + g) * 36 + kc * 8 + ct;
                bf[j][0] = Kf[b0]; bf[j][1] = Kf[b0 + 4];
            }
            #pragma unroll
            for (int j = 0; j < 8; j++) mma16(c[j], af, bf[j]);
        }
        // epilogue: p -> score (fp32, streaming) + pack fp16 A-fragments
        uint32_t plo[8], phi[8];
        {
            int rloc = mb + g;
            float iv0 = invs[rloc], iv1 = invs[rloc + 8];
            int grow = q0 + rloc;
            #pragma unroll
            for (int j = 0; j < 8; j++) {
                int colg = n0 + nb + j * 8 + ct * 2;
                float2 mk0 = __half22float2(*(const __half2*)&g_mh[(size_t)grow * SS + colg]);
                float p0 = pexp(c[j][0], mk0.x) * iv0;
                float p1 = pexp(c[j][1], mk0.y) * iv0;
                stcs2(&score[sbase + (size_t)grow * SS + colg], make_float2(p0, p1));
                float2 mk1 = __half22float2(*(const __half2*)&g_mh[(size_t)(grow + 8) * SS + colg]);
                float p2 = pexp(c[j][2], mk1.x) * iv1;
                float p3 = pexp(c[j][3], mk1.y) * iv1;
                stcs2(&score[sbase + (size_t)(grow + 8) * SS + colg], make_float2(p2, p3));
                plo[j] = h2u(__floats2half2_rn(p0, p1));
                phi[j] = h2u(__floats2half2_rn(p2, p3));
            }
        }
        CP_WAIT1;            // Vt done (K_next may remain in flight)
        __syncthreads();     // Vt visible to all
        // PV: ctx += P @ V ; A = packed p regs, B = V^T smem
        #pragma unroll
        for (int jj = 0; jj < 4; jj++) {
            uint32_t bf[8][2];
            #pragma unroll
            for (int jd = 0; jd < 8; jd++) {
                int b0 = (jd * 8 + g) * 68 + nw * 32 + jj * 8 + ct;
                bf[jd][0] = Vt[b0]; bf[jd][1] = Vt[b0 + 4];
            }
            uint32_t pa[4] = { plo[2 * jj], phi[2 * jj],
                               plo[2 * jj + 1], phi[2 * jj + 1] };
            #pragma unroll
            for (int jd = 0; jd < 8; jd++) mma16(d[jd], pa, bf[jd]);
        }
    }
    #undef KLOAD
    #undef VLOAD
    __syncthreads();
    // ctx reduction across the 2 n-strip warps (redc overlays dead Ks region)
    if (nw == 1) {
        int r0 = mb + g;
        #pragma unroll
        for (int jd = 0; jd < 8; jd++) {
            int col = jd * 8 + ct * 2;
            redc[r0 * 68 + col]           = d[jd][0];
            redc[r0 * 68 + col + 1]       = d[jd][1];
            redc[(r0 + 8) * 68 + col]     = d[jd][2];
            redc[(r0 + 8) * 68 + col + 1] = d[jd][3];
        }
    }
    __syncthreads();
    if (nw == 0) {
        int r0 = mb + g;
        #pragma unroll
        for (int jd = 0; jd < 8; jd++) {
            int col = jd * 8 + ct * 2;
            float v0 = d[jd][0] + redc[r0 * 68 + col];
            float v1 = d[jd][1] + redc[r0 * 68 + col + 1];
            float v2 = d[jd][2] + redc[(r0 + 8) * 68 + col];
            float v3 = d[jd][3] + redc[(r0 + 8) * 68 + col + 1];
            size_t b0 = ((size_t)bh * SS + q0 + r0) * DH + col;
            *(uint32_t*)&g_ctx[b0]          = h2u(__floats2half2_rn(v0, v1));
            *(uint32_t*)&g_ctx[b0 + 8 * DH] = h2u(__floats2half2_rn(v2, v3));
        }
    }
}

// ---------------------------------------------------------------------------
// K4: output projection, fp16. (round-10 proven version)
// ---------------------------------------------------------------------------
__global__ __launch_bounds__(256, 2) void k_oproj(
    const float* __restrict__ bo, float* __restrict__ out)
{
    __shared__ uint32_t As[2][2560];
    __shared__ uint32_t Bs[2][2560];
    int tid = threadIdx.x;
    int lane = tid & 31, wid = tid >> 5;
    int g = lane >> 2, ct = lane & 3;
    int mb = (wid >> 2) * 64, nb = (wid & 3) * 32;
    int m0 = blockIdx.y * 128, n0 = blockIdx.x * 128;

    uint32_t asb = (uint32_t)__cvta_generic_to_shared(&As[0][0]);
    uint32_t bsb = (uint32_t)__cvta_generic_to_shared(&Bs[0][0]);

    float c[4][4][4];
    #pragma unroll
    for (int i = 0; i < 4; i++)
        #pragma unroll
        for (int j = 0; j < 4; j++)
            #pragma unroll
            for (int t = 0; t < 4; t++) c[i][j][t] = 0.0f;

    #define OLOAD(st_, k0_) do {                                                \
        _Pragma("unroll")                                                       \
        for (int it = 0; it < 2; it++) {                                        \
            int sl = tid + it * 256;                                            \
            int r = sl >> 2, ch = sl & 3;                                       \
            int m = m0 + r;                                                     \
            int b_ = m >> 11, s_ = m & (SS - 1);                                \
            int kk = (k0_) + ch * 8;                                            \
            int h = kk >> 6, dhh = kk & 63;                                     \
            cpa16(asb + ((st_) * 2560 + r * 20 + ch * 4) * 4,                   \
                  g_ctx + ((size_t)(b_ * HH + h) * SS + s_) * DH + dhh);        \
            cpa16(bsb + ((st_) * 2560 + r * 20 + ch * 4) * 4,                   \
                  g_wh3 + (size_t)(n0 + r) * DM + (k0_) + ch * 8);              \
        }                                                                       \
    } while (0)

    OLOAD(0, 0);
    CP_COMMIT;

    for (int k0 = 0, st = 0; k0 < DM; k0 += 32, st ^= 1) {
        CP_WAIT0;
        __syncthreads();
        if (k0 + 32 < DM) OLOAD(st ^ 1, k0 + 32);
        CP_COMMIT;
        const uint32_t* Af = &As[st][0];
        const uint32_t* Bf = &Bs[st][0];
        #pragma unroll
        for (int kc = 0; kc < 2; kc++) {
            uint32_t af[4][4], bf[4][2];
            #pragma unroll
            for (int i = 0; i < 4; i++) {
                int r0 = (mb + i * 16 + g) * 20 + kc * 8 + ct;
                af[i][0] = Af[r0];     af[i][1] = Af[r0 + 160];
                af[i][2] = Af[r0 + 4]; af[i][3] = Af[r0 + 164];
            }
            #pragma unroll
            for (int j = 0; j < 4; j++) {
                int b0 = (nb + j * 8 + g) * 20 + kc * 8 + ct;
                bf[j][0] = Bf[b0]; bf[j][1] = Bf[b0 + 4];
            }
            #pragma unroll
            for (int i = 0; i < 4; i++)
                #pragma unroll
                for (int j = 0; j < 4; j++) mma16(c[i][j], af[i], bf[j]);
        }
    }
    #undef OLOAD
    __syncthreads();
    #pragma unroll
    for (int i = 0; i < 4; i++) {
        int row = m0 + mb + i * 16 + g;
        #pragma unroll
        for (int j = 0; j < 4; j++) {
            int col = n0 + nb + j * 8 + ct * 2;
            float2 bi = *(const float2*)&bo[col];
            *(float2*)&out[(size_t)row * DM + col] =
                make_float2(c[i][j][0] + bi.x, c[i][j][1] + bi.y);
            *(float2*)&out[(size_t)(row + 8) * DM + col] =
                make_float2(c[i][j][2] + bi.x, c[i][j][3] + bi.y);
        }
    }
}

// ---------------------------------------------------------------------------
extern "C" void kernel_launch(void* const* d_in, const int* in_sizes, int n_in,
                              void* d_out, int out_size)
{
    const float* q    = (const float*)d_in[0];
    const float* k    = (const float*)d_in[1];
    const float* v    = (const float*)d_in[2];
    const float* mask = (const float*)d_in[3];
    const float* w_q  = (const float*)d_in[4];
    const float* b_q  = (const float*)d_in[5];
    const float* w_k  = (const float*)d_in[6];
    const float* b_k  = (const float*)d_in[7];
    const float* w_v  = (const float*)d_in[8];
    const float* b_v  = (const float*)d_in[9];
    const float* w_o  = (const float*)d_in[10];
    const float* b_o  = (const float*)d_in[11];

    float* out   = (float*)d_out;                        // x: [B,S,DM]
    float* score = out + (size_t)BB * SS * DM;           // score: [B,H,S,S]

    cudaFuncSetAttribute(k_attn, cudaFuncAttributeMaxDynamicSharedMemorySize, AT_BYTES);

    k_prep<<<dim3(4096, 1, 8), 512>>>(q, k, v, w_q, w_k, w_v, w_o, mask);
    k_qkv_proj<<<dim3(DM/128, (BB*SS)/128, 3), 256>>>(b_q, b_k, b_v);
    k_attn<<<dim3(SS/64, BHT), 256, AT_BYTES>>>(score);
    k_oproj<<<dim3(DM/128, (BB*SS)/128), 256>>>(b_o, out);
}

// round 15
// speedup vs baseline: 1.1418x; 1.1418x over previous
#include <cuda_runtime.h>
#include <cuda_fp16.h>
#include <cstdint>

// Problem constants
#define BB   4
#define SS   2048
#define HH   16
#define DH   64
#define DM   1024
#define BHT  (BB*HH)          // 64
#define NX   (BB*SS*DM)       // 8388608
#define NW   (DM*DM)          // 1048576
#define NH   ((size_t)BB*HH*SS*DH)
#define K8E  0.18033688011112042f   // 0.125 * log2(e)
#define L2E  1.4426950408889634f    // log2(e)

// Scratch (device globals, fp16)
__device__ __half g_xh0[NX], g_xh1[NX], g_xh2[NX];            // fp16 inputs
__device__ __half g_wh0[NW], g_wh1[NW], g_wh2[NW], g_wh3[NW]; // fp16 weights
__device__ __half g_qh[NH], g_kh[NH];                         // [bh][s][dh]
__device__ __half g_vt[NH];                                   // [bh][dh][s]  (V^T)
__device__ __half g_ctx[NH];                                  // [bh][s][dh]

// ---------------------------------------------------------------------------
// helpers
// ---------------------------------------------------------------------------
__device__ __forceinline__ void mma16(float c[4], const uint32_t a[4], const uint32_t b[2]) {
    asm volatile(
        "mma.sync.aligned.m16n8k16.row.col.f32.f16.f16.f32 "
        "{%0,%1,%2,%3},{%4,%5,%6,%7},{%8,%9},{%0,%1,%2,%3};"
        : "+f"(c[0]), "+f"(c[1]), "+f"(c[2]), "+f"(c[3])
        : "r"(a[0]), "r"(a[1]), "r"(a[2]), "r"(a[3]), "r"(b[0]), "r"(b[1]));
}
// exp(c*0.125 + m) via base-2 degree-4 Taylor (|f|<=0.5, rel err <= 4.3e-5)
__device__ __forceinline__ float pexp(float c, float m) {
    float y = fmaf(c, K8E, m * L2E);
    float r = rintf(y);
    float f = y - r;
    float p = fmaf(0.009618129f, f, 0.055504109f);
    p = fmaf(p, f, 0.240226507f);
    p = fmaf(p, f, 0.693147181f);
    p = fmaf(p, f, 1.0f);
    return p * __int_as_float(((int)r + 127) << 23);
}
__device__ __forceinline__ void cpa16(uint32_t saddr, const void* g) {
    asm volatile("cp.async.ca.shared.global [%0], [%1], 16;" :: "r"(saddr), "l"(g));
}
#define CP_COMMIT asm volatile("cp.async.commit_group;")
#define CP_WAIT0  asm volatile("cp.async.wait_group 0;")
#define CP_WAIT1  asm volatile("cp.async.wait_group 1;")
__device__ __forceinline__ uint32_t h2u(__half2 h) { return *(uint32_t*)&h; }
// streaming (evict-first) float2 store
__device__ __forceinline__ void stcs2(float* p, float2 v) {
    asm volatile("st.global.cs.v2.f32 [%0], {%1, %2};" :: "l"(p), "f"(v.x), "f"(v.y) : "memory");
}

// ---------------------------------------------------------------------------
// K0: convert inputs + weights to fp16
// ---------------------------------------------------------------------------
__global__ void k_prep(const float* __restrict__ q, const float* __restrict__ k,
                       const float* __restrict__ v, const float* __restrict__ wq,
                       const float* __restrict__ wk, const float* __restrict__ wv,
                       const float* __restrict__ wo)
{
    int z = blockIdx.z;
    size_t i4 = (size_t)blockIdx.x * blockDim.x + threadIdx.x;
    const float4* src; __half* dst; size_t n4;
    switch (z) {
        case 0: src = (const float4*)q;  dst = g_xh0; n4 = NX / 4; break;
        case 1: src = (const float4*)k;  dst = g_xh1; n4 = NX / 4; break;
        case 2: src = (const float4*)v;  dst = g_xh2; n4 = NX / 4; break;
        case 3: src = (const float4*)wq; dst = g_wh0; n4 = NW / 4; break;
        case 4: src = (const float4*)wk; dst = g_wh1; n4 = NW / 4; break;
        case 5: src = (const float4*)wv; dst = g_wh2; n4 = NW / 4; break;
        default: src = (const float4*)wo; dst = g_wh3; n4 = NW / 4; break;
    }
    if (i4 < n4) {
        float4 a = src[i4];
        __half2 lo = __floats2half2_rn(a.x, a.y);
        __half2 hi = __floats2half2_rn(a.z, a.w);
        uint2 w = make_uint2(h2u(lo), h2u(hi));
        *(uint2*)&dst[i4 * 4] = w;
    }
}

// ---------------------------------------------------------------------------
// K1: fused QKV projection, fp16 m16n8k16. BK=64 (4 k16 chunks), dynamic smem
// double buffer (stride 36 words/row, conflict-free).
// ---------------------------------------------------------------------------
#define GJ_STAGE 4608                       // 128 rows * 36 words
#define GJ_BYTES (4 * GJ_STAGE * 4)         // A[2] + B[2]

__global__ __launch_bounds__(256, 2) void k_qkv_proj(
    const float* __restrict__ bq, const float* __restrict__ bk,
    const float* __restrict__ bv)
{
    extern __shared__ uint32_t smj[];
    uint32_t* As = smj;                      // [2][4608]
    uint32_t* Bs = smj + 2 * GJ_STAGE;       // [2][4608]
    int z = blockIdx.z;
    const __half* X  = (z == 0) ? g_xh0 : (z == 1) ? g_xh1 : g_xh2;
    const __half* W  = (z == 0) ? g_wh0 : (z == 1) ? g_wh1 : g_wh2;
    const float*  Bi = (z == 0) ? bq : (z == 1) ? bk : bv;

    int tid = threadIdx.x;
    int lane = tid & 31, wid = tid >> 5;
    int g = lane >> 2, ct = lane & 3;
    int mb = (wid >> 2) * 64, nb = (wid & 3) * 32;
    int m0 = blockIdx.y * 128, n0 = blockIdx.x * 128;

    uint32_t asb = (uint32_t)__cvta_generic_to_shared(As);
    uint32_t bsb = (uint32_t)__cvta_generic_to_shared(Bs);

    float c[4][4][4];
    #pragma unroll
    for (int i = 0; i < 4; i++)
        #pragma unroll
        for (int j = 0; j < 4; j++)
            #pragma unroll
            for (int t = 0; t < 4; t++) c[i][j][t] = 0.0f;

    #define QLOAD(st_, k0_) do {                                                \
        _Pragma("unroll")                                                       \
        for (int it = 0; it < 4; it++) {                                        \
            int sl = tid + it * 256;                                            \
            int r = sl >> 3, ch = sl & 7;                                       \
            cpa16(asb + ((st_) * GJ_STAGE + r * 36 + ch * 4) * 4,               \
                  X + (size_t)(m0 + r) * DM + (k0_) + ch * 8);                  \
            cpa16(bsb + ((st_) * GJ_STAGE + r * 36 + ch * 4) * 4,               \
                  W + (size_t)(n0 + r) * DM + (k0_) + ch * 8);                  \
        }                                                                       \
    } while (0)

    QLOAD(0, 0);
    CP_COMMIT;

    for (int k0 = 0, st = 0; k0 < DM; k0 += 64, st ^= 1) {
        CP_WAIT0;
        __syncthreads();
        if (k0 + 64 < DM) QLOAD(st ^ 1, k0 + 64);
        CP_COMMIT;
        const uint32_t* Af = As + st * GJ_STAGE;
        const uint32_t* Bf = Bs + st * GJ_STAGE;
        #pragma unroll
        for (int kc = 0; kc < 4; kc++) {
            uint32_t af[4][4], bf[4][2];
            #pragma unroll
            for (int i = 0; i < 4; i++) {
                int r0 = (mb + i * 16 + g) * 36 + kc * 8 + ct;
                af[i][0] = Af[r0];       af[i][1] = Af[r0 + 288];
                af[i][2] = Af[r0 + 4];   af[i][3] = Af[r0 + 292];
            }
            #pragma unroll
            for (int j = 0; j < 4; j++) {
                int b0 = (nb + j * 8 + g) * 36 + kc * 8 + ct;
                bf[j][0] = Bf[b0]; bf[j][1] = Bf[b0 + 4];
            }
            #pragma unroll
            for (int i = 0; i < 4; i++)
                #pragma unroll
                for (int j = 0; j < 4; j++) mma16(c[i][j], af[i], bf[j]);
        }
    }
    #undef QLOAD
    __syncthreads();
    #pragma unroll
    for (int i = 0; i < 4; i++) {
        int row = m0 + mb + i * 16 + g;
        int b_ = row >> 11, s_ = row & (SS - 1);
        #pragma unroll
        for (int j = 0; j < 4; j++) {
            int col = n0 + nb + j * 8 + ct * 2;
            int h = col >> 6, dh = col & 63;
            float2 bi = *(const float2*)&Bi[col];
            float v0 = c[i][j][0] + bi.x, v1 = c[i][j][1] + bi.y;
            float v2 = c[i][j][2] + bi.x, v3 = c[i][j][3] + bi.y;
            if (z == 2) {
                size_t tb = ((size_t)(b_ * HH + h) * DH + dh) * SS;
                g_vt[tb + s_]            = __float2half_rn(v0);
                g_vt[tb + SS + s_]       = __float2half_rn(v1);
                g_vt[tb + s_ + 8]        = __float2half_rn(v2);
                g_vt[tb + SS + s_ + 8]   = __float2half_rn(v3);
            } else {
                __half* O = (z == 0) ? g_qh : g_kh;
                size_t base = ((size_t)(b_ * HH + h) * SS + s_) * DH + dh;
                *(uint32_t*)&O[base]          = h2u(__floats2half2_rn(v0, v1));
                *(uint32_t*)&O[base + 8 * DH] = h2u(__floats2half2_rn(v2, v3));
            }
        }
    }
}

// ---------------------------------------------------------------------------
// K2: fused attention (EXACT round-12 best: fp32 mask, pexp, stcs).
// ---------------------------------------------------------------------------
#define AQ  0
#define AK  2304
#define AV  11520
#define ARD AK
#define ARP 15872
#define AIV 16000
#define AT_WORDS 16064
#define AT_BYTES (AT_WORDS * 4)

__global__ __launch_bounds__(256, 2) void k_attn(
    const float* __restrict__ mask, float* __restrict__ score)
{
    extern __shared__ uint32_t sm[];
    uint32_t* Qs = sm + AQ;
    uint32_t* Vt = sm + AV;
    float* redc  = (float*)(sm + ARD);
    float* rowp  = (float*)(sm + ARP);
    float* invs  = (float*)(sm + AIV);
    uint32_t smb = (uint32_t)__cvta_generic_to_shared(sm);

    int bh = blockIdx.y, q0 = blockIdx.x * 64;
    const __half* Q = g_qh + (size_t)bh * SS * DH;
    const __half* K = g_kh + (size_t)bh * SS * DH;
    const __half* V = g_vt + (size_t)bh * DH * SS;   // [dh][s]

    int tid = threadIdx.x, lane = tid & 31, wid = tid >> 5;
    int g = lane >> 2, ct = lane & 3;
    int mb = (wid & 3) * 16;      // q strip (16 rows)
    int nw = wid >> 2;            // n strip 0/1 (64 cols)
    int nb = nw * 64;

    // Q tile -> smem
    #pragma unroll
    for (int it = 0; it < 2; it++) {
        int sl = tid + it * 256;
        int r = sl >> 3, ch = sl & 7;
        cpa16(smb + (AQ + r * 36 + ch * 4) * 4, Q + (size_t)(q0 + r) * DH + ch * 8);
    }

    #define KLOAD(st_, n0_) do {                                                \
        _Pragma("unroll")                                                       \
        for (int it = 0; it < 4; it++) {                                        \
            int sl = tid + it * 256;                                            \
            int r = sl >> 3, ch = sl & 7;                                       \
            cpa16(smb + (AK + (st_) * 4608 + r * 36 + ch * 4) * 4,              \
                  K + (size_t)((n0_) + r) * DH + ch * 8);                       \
        }                                                                       \
    } while (0)
    #define VLOAD(n0_) do {                                                     \
        _Pragma("unroll")                                                       \
        for (int it = 0; it < 4; it++) {                                        \
            int sl = tid + it * 256;                                            \
            int r = sl >> 4, ch = sl & 15;                                      \
            cpa16(smb + (AV + r * 68 + ch * 4) * 4,                             \
                  V + (size_t)r * SS + (n0_) + ch * 8);                         \
        }                                                                       \
    } while (0)

    float c[8][4];
    float rs0 = 0.0f, rs1 = 0.0f;

    // ---------------- Pass A: row sums ----------------
    KLOAD(0, 0);
    CP_COMMIT;
    for (int n0 = 0, st = 0; n0 < SS; n0 += 128, st ^= 1) {
        CP_WAIT0;
        __syncthreads();
        if (n0 + 128 < SS) KLOAD(st ^ 1, n0 + 128);
        CP_COMMIT;
        const uint32_t* Kf = sm + AK + st * 4608;
        #pragma unroll
        for (int j = 0; j < 8; j++)
            #pragma unroll
            for (int t = 0; t < 4; t++) c[j][t] = 0.0f;
        #pragma unroll
        for (int kc = 0; kc < 4; kc++) {
            uint32_t af[4], bf[8][2];
            int r0 = (mb + g) * 36 + kc * 8 + ct;
            af[0] = Qs[r0];     af[1] = Qs[r0 + 288];
            af[2] = Qs[r0 + 4]; af[3] = Qs[r0 + 292];
            #pragma unroll
            for (int j = 0; j < 8; j++) {
                int b0 = (nb + j * 8 + g) * 36 + kc * 8 + ct;
                bf[j][0] = Kf[b0]; bf[j][1] = Kf[b0 + 4];
            }
            #pragma unroll
            for (int j = 0; j < 8; j++) mma16(c[j], af, bf[j]);
        }
        {
            int row = q0 + mb + g;
            #pragma unroll
            for (int j = 0; j < 8; j++) {
                int colg = n0 + nb + j * 8 + ct * 2;
                float2 mk0 = *(const float2*)&mask[(size_t)row * SS + colg];
                rs0 += pexp(c[j][0], mk0.x) + pexp(c[j][1], mk0.y);
                float2 mk1 = *(const float2*)&mask[(size_t)(row + 8) * SS + colg];
                rs1 += pexp(c[j][2], mk1.x) + pexp(c[j][3], mk1.y);
            }
        }
    }
    {
        float v = rs0;
        v += __shfl_xor_sync(0xffffffff, v, 1);
        v += __shfl_xor_sync(0xffffffff, v, 2);
        if (ct == 0) rowp[(mb + g) * 2 + nw] = v;
        v = rs1;
        v += __shfl_xor_sync(0xffffffff, v, 1);
        v += __shfl_xor_sync(0xffffffff, v, 2);
        if (ct == 0) rowp[(mb + 8 + g) * 2 + nw] = v;
    }
    __syncthreads();
    if (tid < 64) invs[tid] = 1.0f / (rowp[tid * 2] + rowp[tid * 2 + 1]);

    // ---------------- Pass B: score + ctx ----------------
    float d[8][4];
    #pragma unroll
    for (int j = 0; j < 8; j++)
        #pragma unroll
        for (int t = 0; t < 4; t++) d[j][t] = 0.0f;

    size_t sbase = (size_t)bh * SS * SS;

    KLOAD(0, 0);
    CP_COMMIT;
    for (int n0 = 0, st = 0; n0 < SS; n0 += 128, st ^= 1) {
        CP_WAIT0;            // K_cur ready
        __syncthreads();     // prev PV readers of Vt done; invs visible (iter 0)
        VLOAD(n0);
        CP_COMMIT;
        if (n0 + 128 < SS) KLOAD(st ^ 1, n0 + 128);
        CP_COMMIT;

        const uint32_t* Kf = sm + AK + st * 4608;
        #pragma unroll
        for (int j = 0; j < 8; j++)
            #pragma unroll
            for (int t = 0; t < 4; t++) c[j][t] = 0.0f;
        #pragma unroll
        for (int kc = 0; kc < 4; kc++) {
            uint32_t af[4], bf[8][2];
            int r0 = (mb + g) * 36 + kc * 8 + ct;
            af[0] = Qs[r0];     af[1] = Qs[r0 + 288];
            af[2] = Qs[r0 + 4]; af[3] = Qs[r0 + 292];
            #pragma unroll
            for (int j = 0; j < 8; j++) {
                int b0 = (nb + j * 8 + g) * 36 + kc * 8 + ct;
                bf[j][0] = Kf[b0]; bf[j][1] = Kf[b0 + 4];
            }
            #pragma unroll
            for (int j = 0; j < 8; j++) mma16(c[j], af, bf[j]);
        }
        // epilogue: p -> score (fp32, streaming) + pack fp16 A-fragments
        uint32_t plo[8], phi[8];
        {
            int rloc = mb + g;
            float iv0 = invs[rloc], iv1 = invs[rloc + 8];
            int grow = q0 + rloc;
            #pragma unroll
            for (int j = 0; j < 8; j++) {
                int colg = n0 + nb + j * 8 + ct * 2;
                float2 mk0 = *(const float2*)&mask[(size_t)grow * SS + colg];
                float p0 = pexp(c[j][0], mk0.x) * iv0;
                float p1 = pexp(c[j][1], mk0.y) * iv0;
                stcs2(&score[sbase + (size_t)grow * SS + colg], make_float2(p0, p1));
                float2 mk1 = *(const float2*)&mask[(size_t)(grow + 8) * SS + colg];
                float p2 = pexp(c[j][2], mk1.x) * iv1;
                float p3 = pexp(c[j][3], mk1.y) * iv1;
                stcs2(&score[sbase + (size_t)(grow + 8) * SS + colg], make_float2(p2, p3));
                plo[j] = h2u(__floats2half2_rn(p0, p1));
                phi[j] = h2u(__floats2half2_rn(p2, p3));
            }
        }
        CP_WAIT1;            // Vt done (K_next may remain in flight)
        __syncthreads();     // Vt visible to all
        // PV: ctx += P @ V ; A = packed p regs, B = V^T smem
        #pragma unroll
        for (int jj = 0; jj < 4; jj++) {
            uint32_t bf[8][2];
            #pragma unroll
            for (int jd = 0; jd < 8; jd++) {
                int b0 = (jd * 8 + g) * 68 + nw * 32 + jj * 8 + ct;
                bf[jd][0] = Vt[b0]; bf[jd][1] = Vt[b0 + 4];
            }
            uint32_t pa[4] = { plo[2 * jj], phi[2 * jj],
                               plo[2 * jj + 1], phi[2 * jj + 1] };
            #pragma unroll
            for (int jd = 0; jd < 8; jd++) mma16(d[jd], pa, bf[jd]);
        }
    }
    #undef KLOAD
    #undef VLOAD
    __syncthreads();
    // ctx reduction across the 2 n-strip warps (redc overlays dead Ks region)
    if (nw == 1) {
        int r0 = mb + g;
        #pragma unroll
        for (int jd = 0; jd < 8; jd++) {
            int col = jd * 8 + ct * 2;
            redc[r0 * 68 + col]           = d[jd][0];
            redc[r0 * 68 + col + 1]       = d[jd][1];
            redc[(r0 + 8) * 68 + col]     = d[jd][2];
            redc[(r0 + 8) * 68 + col + 1] = d[jd][3];
        }
    }
    __syncthreads();
    if (nw == 0) {
        int r0 = mb + g;
        #pragma unroll
        for (int jd = 0; jd < 8; jd++) {
            int col = jd * 8 + ct * 2;
            float v0 = d[jd][0] + redc[r0 * 68 + col];
            float v1 = d[jd][1] + redc[r0 * 68 + col + 1];
            float v2 = d[jd][2] + redc[(r0 + 8) * 68 + col];
            float v3 = d[jd][3] + redc[(r0 + 8) * 68 + col + 1];
            size_t b0 = ((size_t)bh * SS + q0 + r0) * DH + col;
            *(uint32_t*)&g_ctx[b0]          = h2u(__floats2half2_rn(v0, v1));
            *(uint32_t*)&g_ctx[b0 + 8 * DH] = h2u(__floats2half2_rn(v2, v3));
        }
    }
}

// ---------------------------------------------------------------------------
// K4: output projection, fp16, BK=64 (dynamic smem double buffer).
// ---------------------------------------------------------------------------
__global__ __launch_bounds__(256, 2) void k_oproj(
    const float* __restrict__ bo, float* __restrict__ out)
{
    extern __shared__ uint32_t smj[];
    uint32_t* As = smj;
    uint32_t* Bs = smj + 2 * GJ_STAGE;
    int tid = threadIdx.x;
    int lane = tid & 31, wid = tid >> 5;
    int g = lane >> 2, ct = lane & 3;
    int mb = (wid >> 2) * 64, nb = (wid & 3) * 32;
    int m0 = blockIdx.y * 128, n0 = blockIdx.x * 128;

    uint32_t asb = (uint32_t)__cvta_generic_to_shared(As);
    uint32_t bsb = (uint32_t)__cvta_generic_to_shared(Bs);

    float c[4][4][4];
    #pragma unroll
    for (int i = 0; i < 4; i++)
        #pragma unroll
        for (int j = 0; j < 4; j++)
            #pragma unroll
            for (int t = 0; t < 4; t++) c[i][j][t] = 0.0f;

    // k0 is 64-aligned so all 64 k-values in a chunk share one head
    #define OLOAD(st_, k0_) do {                                                \
        int _h = (k0_) >> 6;                                                    \
        _Pragma("unroll")                                                       \
        for (int it = 0; it < 4; it++) {                                        \
            int sl = tid + it * 256;                                            \
            int r = sl >> 3, ch = sl & 7;                                       \
            int m = m0 + r;                                                     \
            int b_ = m >> 11, s_ = m & (SS - 1);                                \
            cpa16(asb + ((st_) * GJ_STAGE + r * 36 + ch * 4) * 4,               \
                  g_ctx + ((size_t)(b_ * HH + _h) * SS + s_) * DH + ch * 8);    \
            cpa16(bsb + ((st_) * GJ_STAGE + r * 36 + ch * 4) * 4,               \
                  g_wh3 + (size_t)(n0 + r) * DM + (k0_) + ch * 8);              \
        }                                                                       \
    } while (0)

    OLOAD(0, 0);
    CP_COMMIT;

    for (int k0 = 0, st = 0; k0 < DM; k0 += 64, st ^= 1) {
        CP_WAIT0;
        __syncthreads();
        if (k0 + 64 < DM) OLOAD(st ^ 1, k0 + 64);
        CP_COMMIT;
        const uint32_t* Af = As + st * GJ_STAGE;
        const uint32_t* Bf = Bs + st * GJ_STAGE;
        #pragma unroll
        for (int kc = 0; kc < 4; kc++) {
            uint32_t af[4][4], bf[4][2];
            #pragma unroll
            for (int i = 0; i < 4; i++) {
                int r0 = (mb + i * 16 + g) * 36 + kc * 8 + ct;
                af[i][0] = Af[r0];     af[i][1] = Af[r0 + 288];
                af[i][2] = Af[r0 + 4]; af[i][3] = Af[r0 + 292];
            }
            #pragma unroll
            for (int j = 0; j < 4; j++) {
                int b0 = (nb + j * 8 + g) * 36 + kc * 8 + ct;
                bf[j][0] = Bf[b0]; bf[j][1] = Bf[b0 + 4];
            }
            #pragma unroll
            for (int i = 0; i < 4; i++)
                #pragma unroll
                for (int j = 0; j < 4; j++) mma16(c[i][j], af[i], bf[j]);
        }
    }
    #undef OLOAD
    __syncthreads();
    #pragma unroll
    for (int i = 0; i < 4; i++) {
        int row = m0 + mb + i * 16 + g;
        #pragma unroll
        for (int j = 0; j < 4; j++) {
            int col = n0 + nb + j * 8 + ct * 2;
            float2 bi = *(const float2*)&bo[col];
            *(float2*)&out[(size_t)row * DM + col] =
                make_float2(c[i][j][0] + bi.x, c[i][j][1] + bi.y);
            *(float2*)&out[(size_t)(row + 8) * DM + col] =
                make_float2(c[i][j][2] + bi.x, c[i][j][3] + bi.y);
        }
    }
}

// ---------------------------------------------------------------------------
extern "C" void kernel_launch(void* const* d_in, const int* in_sizes, int n_in,
                              void* d_out, int out_size)
{
    const float* q    = (const float*)d_in[0];
    const float* k    = (const float*)d_in[1];
    const float* v    = (const float*)d_in[2];
    const float* mask = (const float*)d_in[3];
    const float* w_q  = (const float*)d_in[4];
    const float* b_q  = (const float*)d_in[5];
    const float* w_k  = (const float*)d_in[6];
    const float* b_k  = (const float*)d_in[7];
    const float* w_v  = (const float*)d_in[8];
    const float* b_v  = (const float*)d_in[9];
    const float* w_o  = (const float*)d_in[10];
    const float* b_o  = (const float*)d_in[11];

    float* out   = (float*)d_out;                        // x: [B,S,DM]
    float* score = out + (size_t)BB * SS * DM;           // score: [B,H,S,S]

    cudaFuncSetAttribute(k_attn, cudaFuncAttributeMaxDynamicSharedMemorySize, AT_BYTES);
    cudaFuncSetAttribute(k_qkv_proj, cudaFuncAttributeMaxDynamicSharedMemorySize, GJ_BYTES);
    cudaFuncSetAttribute(k_oproj, cudaFuncAttributeMaxDynamicSharedMemorySize, GJ_BYTES);

    k_prep<<<dim3(4096, 1, 7), 512>>>(q, k, v, w_q, w_k, w_v, w_o);
    k_qkv_proj<<<dim3(DM/128, (BB*SS)/128, 3), 256, GJ_BYTES>>>(b_q, b_k, b_v);
    k_attn<<<dim3(SS/64, BHT), 256, AT_BYTES>>>(mask, score);
    k_oproj<<<dim3(DM/128, (BB*SS)/128), 256, GJ_BYTES>>>(b_o, out);
}